// round 10
// baseline (speedup 1.0000x reference)
#include <cuda_runtime.h>
#include <cuda_bf16.h>
#include <cstdint>

// SpikeEncoder: rates = sigmoid(x @ W^T + b); spikes = (u < rates)
// x: [256,512] f32, W: [2048,512] f32, b: [2048] f32, u: [256,100,2048] f32
// out: spikes [256*100*2048] f32, then rates [256*2048] f32

#define BATCH 256
#define INPUT_DIM 512
#define NUM_NEURONS 2048
#define TIME_STEPS 100

#define TBM 64
#define TBN 64
#define TBK 32
#define NTILES (INPUT_DIM / TBK)   // 16
#define NSTAGE 3

#define ROWF 36                    // padded floats/row: banks (4g+q) bijective,
                                   // and 36*4=144B = 9*16B -> cp.async aligned
#define TILEF (64 * ROWF)          // 2304 floats per (matrix, component) tile
// buffer layout (floats): [Ahi | Alo | Bhi | Blo], stride 4*TILEF
#define BUFF (4 * TILEF)           // 9216 floats
#define SMEM_BYTES (NSTAGE * BUFF * 4)  // 110592 bytes

// Pre-split tf32 components (device scratch; globals are the sanctioned path)
__device__ float g_xhi[BATCH * INPUT_DIM];
__device__ float g_xlo[BATCH * INPUT_DIM];
__device__ float g_Whi[NUM_NEURONS * INPUT_DIM];
__device__ float g_Wlo[NUM_NEURONS * INPUT_DIM];

__device__ __forceinline__ void cp_async16(uint32_t smem_addr, const void* gmem) {
    asm volatile("cp.async.cg.shared.global [%0], [%1], 16;\n"
                 :: "r"(smem_addr), "l"(gmem));
}
__device__ __forceinline__ void cp_commit() {
    asm volatile("cp.async.commit_group;\n" ::: "memory");
}
__device__ __forceinline__ void cp_wait1() {
    asm volatile("cp.async.wait_group 1;\n" ::: "memory");
}

// fp32 -> tf32 3-term split: v ~= hi + lo, |err| <= ~2^-22 |v|
__device__ __forceinline__ void tf32_split(float v, float& h, float& l) {
    uint32_t hb, lb;
    asm("cvt.rna.tf32.f32 %0, %1;" : "=r"(hb) : "f"(v));
    const float hf = __uint_as_float(hb);
    asm("cvt.rna.tf32.f32 %0, %1;" : "=r"(lb) : "f"(v - hf));
    h = hf;
    l = __uint_as_float(lb);
}

// D += A(tf32, m16k8 row) x B(tf32, k8n8 col)
__device__ __forceinline__ void mma_tf32(float c[4],
                                         uint32_t a0, uint32_t a1,
                                         uint32_t a2, uint32_t a3,
                                         uint32_t b0, uint32_t b1) {
    asm volatile(
        "mma.sync.aligned.m16n8k8.row.col.f32.tf32.tf32.f32 "
        "{%0,%1,%2,%3}, {%4,%5,%6,%7}, {%8,%9}, {%0,%1,%2,%3};"
        : "+f"(c[0]), "+f"(c[1]), "+f"(c[2]), "+f"(c[3])
        : "r"(a0), "r"(a1), "r"(a2), "r"(a3), "r"(b0), "r"(b1));
}

// ---------------------------------------------------------------------------
// Kernel 0: one-shot tf32 split of x and W into device scratch.
// Streaming hints (__ldcs/__stcs) avoid L2 write-allocate; 2 float4 per
// thread for load-level parallelism. 294912 float4 / 2 -> 576 blocks.
// ---------------------------------------------------------------------------
#define X4 (BATCH * INPUT_DIM / 4)        // 32768
#define W4 (NUM_NEURONS * INPUT_DIM / 4)  // 262144

__device__ __forceinline__ void split_store(const float4* __restrict__ src,
                                            float4* __restrict__ hi,
                                            float4* __restrict__ lo, int i) {
    const float4 v = __ldcs(&src[i]);
    float4 h, l;
    tf32_split(v.x, h.x, l.x);
    tf32_split(v.y, h.y, l.y);
    tf32_split(v.z, h.z, l.z);
    tf32_split(v.w, h.w, l.w);
    __stcs(&hi[i], h);
    __stcs(&lo[i], l);
}

__global__ __launch_bounds__(256)
void split_kernel(const float4* __restrict__ x, const float4* __restrict__ W) {
    const int base = blockIdx.x * 512 + threadIdx.x;
#pragma unroll
    for (int l = 0; l < 2; l++) {
        const int i = base + l * 256;
        if (i < X4) {
            split_store(x, (float4*)g_xhi, (float4*)g_xlo, i);
        } else {
            split_store(W, (float4*)g_Whi, (float4*)g_Wlo, i - X4);
        }
    }
}

// ---------------------------------------------------------------------------
// Kernel A: rates = sigmoid(x @ W^T + b), tf32 MMA with 3-term compensation
// (xh*Wh + xh*Wl + xl*Wh), fp32 accum. Tensor-core accumulation rounds RZ,
// so hi*hi is split across TWO accumulator sets (even/odd k8 steps) and the
// cross terms use a third; combined in RN fp32 at the epilogue.
// 64x64 tile, 256 threads, 8 warps (m16 x n32 each), 3-stage cp.async
// pipeline from the pre-split arrays. grid (32, 4).
// PDL: gridsync at start (waits for split) AFTER coord setup; PLC at END
// (spike grid's gridsync must order after rates writes).
// ---------------------------------------------------------------------------
__global__ __launch_bounds__(256)
void rates_kernel(const float* __restrict__ bias,
                  float* __restrict__ rates) {
    extern __shared__ float sm[];

    const int tid  = threadIdx.x;
    const int warp = tid >> 5;
    const int lane = tid & 31;
    const int g = lane >> 2;       // fragment row
    const int q = lane & 3;        // fragment k/col
    const int mb = warp & 3;       // m16 block (0..3)
    const int nh = warp >> 2;      // n32 half (0..1)

    const int nBase = blockIdx.x * TBN;
    const int mBase = blockIdx.y * TBM;

    // Cooperative copy coords: 512 16B-chunks per (matrix,component) tile,
    // 2 per thread per array (4 arrays -> 8 cp.async per stage per thread).
    int row[2], kc[2];
    uint32_t dOff[2];
    const uint32_t sBase = (uint32_t)__cvta_generic_to_shared(sm);
#pragma unroll
    for (int l = 0; l < 2; l++) {
        const int f = tid + l * 256;
        row[l] = f >> 3;           // 0..63
        kc[l]  = (f & 7) * 4;      // 0,4,...,28
        dOff[l] = (uint32_t)(row[l] * ROWF + kc[l]) * 4u;
    }
    const uint32_t tileB = (uint32_t)TILEF * 4u;
    const uint32_t bufB  = (uint32_t)BUFF * 4u;

    // Accumulators: c0/c1 = hi*hi even/odd k8 steps; cx = cross terms
    float c0[4][4], c1[4][4], cx[4][4];
#pragma unroll
    for (int nb = 0; nb < 4; nb++)
#pragma unroll
        for (int e = 0; e < 4; e++) { c0[nb][e] = 0.f; c1[nb][e] = 0.f; cx[nb][e] = 0.f; }

    const int ar0 = (mb * 16 + g) * ROWF;
    const int ar1 = ar0 + 8 * ROWF;

    // Wait for split_kernel's writes (PDL); all setup above overlaps it.
#if __CUDA_ARCH__ >= 900
    cudaGridDependencySynchronize();
#endif

    // Issue stages 0 and 1
#pragma unroll
    for (int p = 0; p < 2; p++) {
        const int k0 = p * TBK;
        const uint32_t sb = sBase + (uint32_t)p * bufB;
#pragma unroll
        for (int l = 0; l < 2; l++) {
            const int ax = (mBase + row[l]) * INPUT_DIM + k0 + kc[l];
            const int bx = (nBase + row[l]) * INPUT_DIM + k0 + kc[l];
            cp_async16(sb + dOff[l],             &g_xhi[ax]);
            cp_async16(sb + tileB + dOff[l],     &g_xlo[ax]);
            cp_async16(sb + 2 * tileB + dOff[l], &g_Whi[bx]);
            cp_async16(sb + 3 * tileB + dOff[l], &g_Wlo[bx]);
        }
        cp_commit();
    }

    for (int t = 0; t < NTILES; t++) {
        cp_wait1();
        __syncthreads();

        if (t + 2 < NTILES) {
            const int k0 = (t + 2) * TBK;
            const uint32_t sb = sBase + (uint32_t)((t + 2) % NSTAGE) * bufB;
#pragma unroll
            for (int l = 0; l < 2; l++) {
                const int ax = (mBase + row[l]) * INPUT_DIM + k0 + kc[l];
                const int bx = (nBase + row[l]) * INPUT_DIM + k0 + kc[l];
                cp_async16(sb + dOff[l],             &g_xhi[ax]);
                cp_async16(sb + tileB + dOff[l],     &g_xlo[ax]);
                cp_async16(sb + 2 * tileB + dOff[l], &g_Whi[bx]);
                cp_async16(sb + 3 * tileB + dOff[l], &g_Wlo[bx]);
            }
            cp_commit();
        }

        const float* base = sm + (t % NSTAGE) * BUFF;
        const float* Ahi = base;
        const float* Alo = base + TILEF;
        const float* Bhi = base + 2 * TILEF;
        const float* Blo = base + 3 * TILEF;

#pragma unroll
        for (int s = 0; s < 4; s++) {           // 4 k8 steps per tile
            const int ka = s * 8 + q;
            const uint32_t a0h = __float_as_uint(Ahi[ar0 + ka]);
            const uint32_t a1h = __float_as_uint(Ahi[ar1 + ka]);
            const uint32_t a2h = __float_as_uint(Ahi[ar0 + ka + 4]);
            const uint32_t a3h = __float_as_uint(Ahi[ar1 + ka + 4]);
            const uint32_t a0l = __float_as_uint(Alo[ar0 + ka]);
            const uint32_t a1l = __float_as_uint(Alo[ar1 + ka]);
            const uint32_t a2l = __float_as_uint(Alo[ar0 + ka + 4]);
            const uint32_t a3l = __float_as_uint(Alo[ar1 + ka + 4]);

            float (*cm)[4] = (s & 1) ? c1 : c0;

#pragma unroll
            for (int nb = 0; nb < 4; nb++) {
                const int rb = (nh * 32 + nb * 8 + g) * ROWF + ka;
                const uint32_t b0h = __float_as_uint(Bhi[rb]);
                const uint32_t b1h = __float_as_uint(Bhi[rb + 4]);
                const uint32_t b0l = __float_as_uint(Blo[rb]);
                const uint32_t b1l = __float_as_uint(Blo[rb + 4]);

                mma_tf32(cm[nb], a0h, a1h, a2h, a3h, b0h, b1h);  // hi*hi
                mma_tf32(cx[nb], a0h, a1h, a2h, a3h, b0l, b1l);  // hi*lo
                mma_tf32(cx[nb], a0l, a1l, a2l, a3l, b0h, b1h);  // lo*hi
            }
        }
    }

    // Epilogue: combine (RN), bias + sigmoid.
    // c[nb]: {C[g][2q], C[g][2q+1], C[g+8][2q], C[g+8][2q+1]}
    const int m1 = mBase + mb * 16 + g;
    const int m2 = m1 + 8;
#pragma unroll
    for (int nb = 0; nb < 4; nb++) {
        const int col = nBase + nh * 32 + nb * 8 + 2 * q;
        const float2 bb = *(const float2*)&bias[col];

        const float z0 = (c0[nb][0] + c1[nb][0]) + cx[nb][0] + bb.x;
        const float z1 = (c0[nb][1] + c1[nb][1]) + cx[nb][1] + bb.y;
        const float z2 = (c0[nb][2] + c1[nb][2]) + cx[nb][2] + bb.x;
        const float z3 = (c0[nb][3] + c1[nb][3]) + cx[nb][3] + bb.y;

        float2 o1, o2;
        o1.x = 1.0f / (1.0f + expf(-z0));
        o1.y = 1.0f / (1.0f + expf(-z1));
        o2.x = 1.0f / (1.0f + expf(-z2));
        o2.y = 1.0f / (1.0f + expf(-z3));

        *(float2*)&rates[m1 * NUM_NEURONS + col] = o1;
        *(float2*)&rates[m2 * NUM_NEURONS + col] = o2;
    }

    // AFTER rates are written: release the dependent spike grid.
#if __CUDA_ARCH__ >= 900
    cudaTriggerProgrammaticLaunchCompletion();
#endif
}

// ---------------------------------------------------------------------------
// Kernel B: streaming spike compare (~61.7us @75% DRAM — at roofline).
// grid (T, BATCH), 256 threads; one (b,t) neuron row per block.
// u loads issued BEFORE the PDL dependency sync; rates read after.
// ---------------------------------------------------------------------------
__global__ __launch_bounds__(256)
void spike_kernel(const float4* __restrict__ u,
                  const float4* __restrict__ rates,
                  float4* __restrict__ spikes) {
    const int b = blockIdx.y;
    const long long base = (long long)(b * TIME_STEPS + blockIdx.x) * (NUM_NEURONS / 4);
    const int j = threadIdx.x * 2;

    const float4 u0 = __ldcs(&u[base + j]);
    const float4 u1 = __ldcs(&u[base + j + 1]);

#if __CUDA_ARCH__ >= 900
    cudaGridDependencySynchronize();
#endif

    const float4* rrow = rates + b * (NUM_NEURONS / 4);
    const float4 r0 = __ldg(&rrow[j]);
    const float4 r1 = __ldg(&rrow[j + 1]);

    float4 s0, s1;
    s0.x = (u0.x < r0.x) ? 1.0f : 0.0f;
    s0.y = (u0.y < r0.y) ? 1.0f : 0.0f;
    s0.z = (u0.z < r0.z) ? 1.0f : 0.0f;
    s0.w = (u0.w < r0.w) ? 1.0f : 0.0f;
    s1.x = (u1.x < r1.x) ? 1.0f : 0.0f;
    s1.y = (u1.y < r1.y) ? 1.0f : 0.0f;
    s1.z = (u1.z < r1.z) ? 1.0f : 0.0f;
    s1.w = (u1.w < r1.w) ? 1.0f : 0.0f;

    __stcs(&spikes[base + j], s0);
    __stcs(&spikes[base + j + 1], s1);
}

extern "C" void kernel_launch(void* const* d_in, const int* in_sizes, int n_in,
                              void* d_out, int out_size) {
    const float* x = (const float*)d_in[0];
    const float* W = (const float*)d_in[1];
    const float* b = (const float*)d_in[2];
    const float* u = (const float*)d_in[3];

    float* out    = (float*)d_out;
    float* spikes = out;                                               // 52,428,800
    float* rates  = out + (long long)BATCH * TIME_STEPS * NUM_NEURONS; // +524,288

    cudaFuncSetAttribute(rates_kernel,
                         cudaFuncAttributeMaxDynamicSharedMemorySize, SMEM_BYTES);

    // 0) one-shot tf32 split of x and W into device scratch (streaming)
    split_kernel<<<(X4 + W4) / 512, 256>>>((const float4*)x, (const float4*)W);

    // 1) tensor-core rates GEMM — PDL-launched so setup overlaps split tail
    dim3 gridA(NUM_NEURONS / TBN, BATCH / TBM);   // (32, 4)
    {
        cudaLaunchConfig_t cfgA = {};
        cfgA.gridDim  = gridA;
        cfgA.blockDim = dim3(256, 1, 1);
        cfgA.dynamicSmemBytes = SMEM_BYTES;
        cfgA.stream = 0;
        cudaLaunchAttribute attrsA[1];
        attrsA[0].id = cudaLaunchAttributeProgrammaticStreamSerialization;
        attrsA[0].val.programmaticStreamSerializationAllowed = 1;
        cfgA.attrs = attrsA;
        cfgA.numAttrs = 1;
        cudaError_t eA = cudaLaunchKernelEx(&cfgA, rates_kernel, (const float*)b, rates);
        if (eA != cudaSuccess) {
            (void)cudaGetLastError();
            rates_kernel<<<gridA, 256, SMEM_BYTES>>>(b, rates);
        }
    }

    // 2) spike stream with PDL
    const float4* u4 = (const float4*)u;
    const float4* r4 = (const float4*)rates;
    float4*       s4 = (float4*)spikes;

    cudaLaunchConfig_t cfg = {};
    cfg.gridDim  = dim3(TIME_STEPS, BATCH, 1);    // (100, 256)
    cfg.blockDim = dim3(256, 1, 1);
    cfg.dynamicSmemBytes = 0;
    cfg.stream = 0;
    cudaLaunchAttribute attrs[1];
    attrs[0].id = cudaLaunchAttributeProgrammaticStreamSerialization;
    attrs[0].val.programmaticStreamSerializationAllowed = 1;
    cfg.attrs = attrs;
    cfg.numAttrs = 1;

    cudaError_t e = cudaLaunchKernelEx(&cfg, spike_kernel, u4, r4, s4);
    if (e != cudaSuccess) {
        (void)cudaGetLastError();  // clear
        spike_kernel<<<dim3(TIME_STEPS, BATCH, 1), 256>>>(u4, r4, s4);
    }
}

// round 11
// speedup vs baseline: 1.0090x; 1.0090x over previous
#include <cuda_runtime.h>
#include <cuda_bf16.h>
#include <cstdint>

// SpikeEncoder: rates = sigmoid(x @ W^T + b); spikes = (u < rates)
// x: [256,512] f32, W: [2048,512] f32, b: [2048] f32, u: [256,100,2048] f32
// out: spikes [256*100*2048] f32, then rates [256*2048] f32

#define BATCH 256
#define INPUT_DIM 512
#define NUM_NEURONS 2048
#define TIME_STEPS 100

#define TBM 64
#define TBN 64
#define TBK 32
#define NTILES (INPUT_DIM / TBK)   // 16

#define ROWF 36                    // padded floats per smem row (bank-bijective)
#define TILEF (64 * ROWF)          // 2304 floats per (matrix, component) tile
// smem buffer layout (floats): [buf][Ahi | Alo | Bhi | Blo], buf stride 4*TILEF
#define BUFF (4 * TILEF)           // 9216 floats
#define SMEM_BYTES (2 * BUFF * 4)  // 73728 bytes

// fp32 -> tf32 split via mantissa mask (tf32 = fp32 with low 13 mantissa bits
// ignored by the MMA). hi is ONE LOP3 (exact; hi+lo == v exactly); lo is
// rounded to tf32 with cvt.rna so its representation error is ~2^-21|v|.
__device__ __forceinline__ void tf32_split(float v, float& h, float& l) {
    const float hf = __uint_as_float(__float_as_uint(v) & 0xFFFFE000u);
    uint32_t lb;
    asm("cvt.rna.tf32.f32 %0, %1;" : "=r"(lb) : "f"(v - hf));
    h = hf;
    l = __uint_as_float(lb);
}

__device__ __forceinline__ void cvt_store(float* __restrict__ hi,
                                          float* __restrict__ lo,
                                          int off, float4 v) {
    float4 h, l;
    tf32_split(v.x, h.x, l.x);
    tf32_split(v.y, h.y, l.y);
    tf32_split(v.z, h.z, l.z);
    tf32_split(v.w, h.w, l.w);
    *(float4*)&hi[off] = h;
    *(float4*)&lo[off] = l;
}

// D += A(tf32, m16k8 row) x B(tf32, k8n8 col)
__device__ __forceinline__ void mma_tf32(float c[4],
                                         uint32_t a0, uint32_t a1,
                                         uint32_t a2, uint32_t a3,
                                         uint32_t b0, uint32_t b1) {
    asm volatile(
        "mma.sync.aligned.m16n8k8.row.col.f32.tf32.tf32.f32 "
        "{%0,%1,%2,%3}, {%4,%5,%6,%7}, {%8,%9}, {%0,%1,%2,%3};"
        : "+f"(c[0]), "+f"(c[1]), "+f"(c[2]), "+f"(c[3])
        : "r"(a0), "r"(a1), "r"(a2), "r"(a3), "r"(b0), "r"(b1));
}

// ---------------------------------------------------------------------------
// Kernel A: rates = sigmoid(x @ W^T + b) via tf32 tensor-core MMA with
// 3-term error compensation (xh*Wh + xh*Wl + xl*Wh), fp32 accumulators.
// Tensor-core accumulation rounds RZ, so hi*hi is split across TWO
// accumulator sets (even/odd k8 steps, 32-chain each); cross terms use a
// third set (tiny magnitude -> bias negligible); combined RN at epilogue.
// 64x64 tile, 256 threads, 8 warps (m16 x n32 each). K-tile 32 (4 k8 steps),
// double-buffered smem, split-at-store (mask+sub+cvt). grid (32, 4).
// PLC at kernel END (spike grid's gridsync orders after rates writes).
// ---------------------------------------------------------------------------
__global__ __launch_bounds__(256)
void rates_kernel(const float* __restrict__ x,
                  const float* __restrict__ W,
                  const float* __restrict__ bias,
                  float* __restrict__ rates) {
    extern __shared__ float sm[];

    const int tid  = threadIdx.x;
    const int warp = tid >> 5;
    const int lane = tid & 31;
    const int g = lane >> 2;       // fragment row
    const int q = lane & 3;        // fragment k/col
    const int mb = warp & 3;       // m16 block (0..3)
    const int nh = warp >> 2;      // n32 half (0..1)

    const int nBase = blockIdx.x * TBN;
    const int mBase = blockIdx.y * TBM;

    // Cooperative-load coords: 512 float4 per matrix per tile, 2 per thread
    int row[2], kc[2];
#pragma unroll
    for (int l = 0; l < 2; l++) {
        const int f = tid + l * 256;
        row[l] = f >> 3;           // 0..63
        kc[l]  = (f & 7) * 4;      // 0,4,...,28
    }

    // Prologue: tile 0 -> regs -> split -> smem buf 0
    float4 xa[2], wb[2];
#pragma unroll
    for (int l = 0; l < 2; l++) {
        xa[l] = *(const float4*)&x[(mBase + row[l]) * INPUT_DIM + kc[l]];
        wb[l] = *(const float4*)&W[(nBase + row[l]) * INPUT_DIM + kc[l]];
    }
    {
        float* Ahi = sm;            float* Alo = sm + TILEF;
        float* Bhi = sm + 2*TILEF;  float* Blo = sm + 3*TILEF;
#pragma unroll
        for (int l = 0; l < 2; l++) {
            const int off = row[l] * ROWF + kc[l];
            cvt_store(Ahi, Alo, off, xa[l]);
            cvt_store(Bhi, Blo, off, wb[l]);
        }
    }
    __syncthreads();

    // Accumulators: c0/c1 = hi*hi even/odd k8 steps; cx = cross terms
    float c0[4][4], c1[4][4], cx[4][4];
#pragma unroll
    for (int nb = 0; nb < 4; nb++)
#pragma unroll
        for (int e = 0; e < 4; e++) { c0[nb][e] = 0.f; c1[nb][e] = 0.f; cx[nb][e] = 0.f; }

    const int ar0 = (mb * 16 + g) * ROWF;       // A fragment row g
    const int ar1 = ar0 + 8 * ROWF;             // A fragment row g+8

    for (int t = 0; t < NTILES; t++) {
        const float* base = sm + (t & 1) * BUFF;
        const float* Ahi = base;
        const float* Alo = base + TILEF;
        const float* Bhi = base + 2 * TILEF;
        const float* Blo = base + 3 * TILEF;

        // Prefetch next tile gmem -> regs (hidden behind MMA compute)
        if (t < NTILES - 1) {
            const int k0 = (t + 1) * TBK;
#pragma unroll
            for (int l = 0; l < 2; l++) {
                xa[l] = *(const float4*)&x[(mBase + row[l]) * INPUT_DIM + k0 + kc[l]];
                wb[l] = *(const float4*)&W[(nBase + row[l]) * INPUT_DIM + k0 + kc[l]];
            }
        }

#pragma unroll
        for (int s = 0; s < 4; s++) {           // 4 k8 steps per tile
            const int ka = s * 8 + q;
            const uint32_t a0h = __float_as_uint(Ahi[ar0 + ka]);
            const uint32_t a1h = __float_as_uint(Ahi[ar1 + ka]);
            const uint32_t a2h = __float_as_uint(Ahi[ar0 + ka + 4]);
            const uint32_t a3h = __float_as_uint(Ahi[ar1 + ka + 4]);
            const uint32_t a0l = __float_as_uint(Alo[ar0 + ka]);
            const uint32_t a1l = __float_as_uint(Alo[ar1 + ka]);
            const uint32_t a2l = __float_as_uint(Alo[ar0 + ka + 4]);
            const uint32_t a3l = __float_as_uint(Alo[ar1 + ka + 4]);

            float (*cm)[4] = (s & 1) ? c1 : c0;

#pragma unroll
            for (int nb = 0; nb < 4; nb++) {
                const int rb = (nh * 32 + nb * 8 + g) * ROWF + ka;
                const uint32_t b0h = __float_as_uint(Bhi[rb]);
                const uint32_t b1h = __float_as_uint(Bhi[rb + 4]);
                const uint32_t b0l = __float_as_uint(Blo[rb]);
                const uint32_t b1l = __float_as_uint(Blo[rb + 4]);

                mma_tf32(cm[nb], a0h, a1h, a2h, a3h, b0h, b1h);  // hi*hi
                mma_tf32(cx[nb], a0h, a1h, a2h, a3h, b0l, b1l);  // hi*lo
                mma_tf32(cx[nb], a0l, a1l, a2l, a3l, b0h, b1h);  // lo*hi
            }
        }

        // Split+store prefetched tile into the other buffer, then sync
        if (t < NTILES - 1) {
            float* nbuf = sm + ((t + 1) & 1) * BUFF;
            float* Ah = nbuf;            float* Al = nbuf + TILEF;
            float* Bh = nbuf + 2*TILEF;  float* Bl = nbuf + 3*TILEF;
#pragma unroll
            for (int l = 0; l < 2; l++) {
                const int off = row[l] * ROWF + kc[l];
                cvt_store(Ah, Al, off, xa[l]);
                cvt_store(Bh, Bl, off, wb[l]);
            }
            __syncthreads();
        }
    }

    // Epilogue: combine (RN), bias + sigmoid (__expf: rate err ~1e-6, OK).
    // c[nb]: {C[g][2q], C[g][2q+1], C[g+8][2q], C[g+8][2q+1]}
    const int m1 = mBase + mb * 16 + g;
    const int m2 = m1 + 8;
#pragma unroll
    for (int nb = 0; nb < 4; nb++) {
        const int col = nBase + nh * 32 + nb * 8 + 2 * q;
        const float2 bb = *(const float2*)&bias[col];

        const float z0 = (c0[nb][0] + c1[nb][0]) + cx[nb][0] + bb.x;
        const float z1 = (c0[nb][1] + c1[nb][1]) + cx[nb][1] + bb.y;
        const float z2 = (c0[nb][2] + c1[nb][2]) + cx[nb][2] + bb.x;
        const float z3 = (c0[nb][3] + c1[nb][3]) + cx[nb][3] + bb.y;

        float2 o1, o2;
        o1.x = 1.0f / (1.0f + __expf(-z0));
        o1.y = 1.0f / (1.0f + __expf(-z1));
        o2.x = 1.0f / (1.0f + __expf(-z2));
        o2.y = 1.0f / (1.0f + __expf(-z3));

        *(float2*)&rates[m1 * NUM_NEURONS + col] = o1;
        *(float2*)&rates[m2 * NUM_NEURONS + col] = o2;
    }

    // AFTER rates are written: release the dependent spike grid.
#if __CUDA_ARCH__ >= 900
    cudaTriggerProgrammaticLaunchCompletion();
#endif
}

// ---------------------------------------------------------------------------
// Kernel B: streaming spike compare (~61.7us @75% DRAM — at roofline).
// grid (T, BATCH), 256 threads; one (b,t) neuron row per block.
// u loads issued BEFORE the PDL dependency sync; rates read after.
// ---------------------------------------------------------------------------
__global__ __launch_bounds__(256)
void spike_kernel(const float4* __restrict__ u,
                  const float4* __restrict__ rates,
                  float4* __restrict__ spikes) {
    const int b = blockIdx.y;
    const long long base = (long long)(b * TIME_STEPS + blockIdx.x) * (NUM_NEURONS / 4);
    const int j = threadIdx.x * 2;

    const float4 u0 = __ldcs(&u[base + j]);
    const float4 u1 = __ldcs(&u[base + j + 1]);

#if __CUDA_ARCH__ >= 900
    cudaGridDependencySynchronize();
#endif

    const float4* rrow = rates + b * (NUM_NEURONS / 4);
    const float4 r0 = __ldg(&rrow[j]);
    const float4 r1 = __ldg(&rrow[j + 1]);

    float4 s0, s1;
    s0.x = (u0.x < r0.x) ? 1.0f : 0.0f;
    s0.y = (u0.y < r0.y) ? 1.0f : 0.0f;
    s0.z = (u0.z < r0.z) ? 1.0f : 0.0f;
    s0.w = (u0.w < r0.w) ? 1.0f : 0.0f;
    s1.x = (u1.x < r1.x) ? 1.0f : 0.0f;
    s1.y = (u1.y < r1.y) ? 1.0f : 0.0f;
    s1.z = (u1.z < r1.z) ? 1.0f : 0.0f;
    s1.w = (u1.w < r1.w) ? 1.0f : 0.0f;

    __stcs(&spikes[base + j], s0);
    __stcs(&spikes[base + j + 1], s1);
}

extern "C" void kernel_launch(void* const* d_in, const int* in_sizes, int n_in,
                              void* d_out, int out_size) {
    const float* x = (const float*)d_in[0];
    const float* W = (const float*)d_in[1];
    const float* b = (const float*)d_in[2];
    const float* u = (const float*)d_in[3];

    float* out    = (float*)d_out;
    float* spikes = out;                                               // 52,428,800
    float* rates  = out + (long long)BATCH * TIME_STEPS * NUM_NEURONS; // +524,288

    cudaFuncSetAttribute(rates_kernel,
                         cudaFuncAttributeMaxDynamicSharedMemorySize, SMEM_BYTES);

    dim3 gridA(NUM_NEURONS / TBN, BATCH / TBM);   // (32, 4)
    rates_kernel<<<gridA, 256, SMEM_BYTES>>>(x, W, b, rates);

    const float4* u4 = (const float4*)u;
    const float4* r4 = (const float4*)rates;
    float4*       s4 = (float4*)spikes;

    cudaLaunchConfig_t cfg = {};
    cfg.gridDim  = dim3(TIME_STEPS, BATCH, 1);    // (100, 256)
    cfg.blockDim = dim3(256, 1, 1);
    cfg.dynamicSmemBytes = 0;
    cfg.stream = 0;
    cudaLaunchAttribute attrs[1];
    attrs[0].id = cudaLaunchAttributeProgrammaticStreamSerialization;
    attrs[0].val.programmaticStreamSerializationAllowed = 1;
    cfg.attrs = attrs;
    cfg.numAttrs = 1;

    cudaError_t e = cudaLaunchKernelEx(&cfg, spike_kernel, u4, r4, s4);
    if (e != cudaSuccess) {
        (void)cudaGetLastError();  // clear
        spike_kernel<<<dim3(TIME_STEPS, BATCH, 1), 256>>>(u4, r4, s4);
    }
}